// round 14
// baseline (speedup 1.0000x reference)
#include <cuda_runtime.h>
#include <cstdint>

#define NB      128
#define CG      2              // block-columns per CTA
#define GROUPS  (NB / CG)      // 64
#define GCOLS   (CG * 32)      // 64
#define NTHR    256
#define MAXL    160
#define N_DIM   4096
#define BATCH   1024
#define NBLKS   4096

// SMEM layout (bytes, from dynamic base)
#define XS_STRIDE  36          // 36 mod 32 = 4 -> 4nq+kq bijective: conflict-free
#define XS_SLOT    (128 * XS_STRIDE * 4)   // 18432
#define XS_RING    3
// Paired tf32 B: 16 pair-rows x 32 float2; pitch 36 float2 (>=32 capacity,
// mod 16 == 4 -> conflict-free LDS.64).
#define BP_PITCH   36
#define BP_SLOT    (16 * BP_PITCH * 8)     // 4608
#define BP_RING    4
#define XS_OFF     0u
#define BP_OFF     (XS_RING * XS_SLOT)               // 55296
#define LIST_OFF   (BP_OFF + BP_RING * BP_SLOT)      // 73728
#define BIAS_OFF   (LIST_OFF + 4u * MAXL)            // 74368
#define SMEM_DYN   (BIAS_OFF + 4u * GCOLS)           // 74624 -> 3 CTAs/SM fits

// Pre-converted paired-tf32 kernel blocks: [block][pr (16)][float4 chunk (16)]
__device__ float4 g_bp[NBLKS * 256];            // 16 MB
// Pre-converted tf32 x, same layout as x: [BATCH][N_DIM]
__device__ float4 g_xt[BATCH * N_DIM / 4];      // 16 MB

// ---------------- helpers ----------------

__device__ __forceinline__ uint32_t smem_u32(const void* p) {
    uint32_t a;
    asm("{ .reg .u64 t; cvta.to.shared.u64 t, %1; cvt.u32.u64 %0, t; }" : "=r"(a) : "l"(p));
    return a;
}
__device__ __forceinline__ void cpa16(uint32_t dst, const void* src) {
    asm volatile("cp.async.ca.shared.global [%0], [%1], 16;" :: "r"(dst), "l"(src));
}
#define CP_COMMIT() asm volatile("cp.async.commit_group;" ::: "memory")
#define CP_WAIT1()  asm volatile("cp.async.wait_group 1;" ::: "memory")

__device__ __forceinline__ uint32_t lds32i(uint32_t a) {
    uint32_t v;
    asm volatile("ld.shared.b32 %0, [%1];" : "=r"(v) : "r"(a));
    return v;
}
__device__ __forceinline__ void lds64(uint32_t a, uint32_t& r0, uint32_t& r1) {
    asm volatile("ld.shared.v2.b32 {%0,%1}, [%2];" : "=r"(r0), "=r"(r1) : "r"(a));
}
// cvt.rna.tf32.f32 requires a .b32 destination register -> "=r"
__device__ __forceinline__ uint32_t tf32b(float a) {
    uint32_t r;
    asm("cvt.rna.tf32.f32 %0, %1;" : "=r"(r) : "f"(a));
    return r;
}

#define MMA_TF32(C, A0, A1, A2, A3, B0, B1)                                       \
    asm volatile("mma.sync.aligned.m16n8k8.row.col.f32.tf32.tf32.f32 "            \
                 "{%0,%1,%2,%3},{%4,%5,%6,%7},{%8,%9},{%0,%1,%2,%3};"             \
                 : "+f"((C)[0]), "+f"((C)[1]), "+f"((C)[2]), "+f"((C)[3])         \
                 : "r"(A0), "r"(A1), "r"(A2), "r"(A3), "r"(B0), "r"(B1))

// ---------------- prep kernels ----------------

// Reformat kern -> g_bp (tf32, paired fragment layout). One float4 per thread.
__global__ void convert_b_kernel(const float* __restrict__ kern) {
    int idx = blockIdx.x * 256 + threadIdx.x;     // 0 .. NBLKS*256-1
    int n  = idx >> 8;
    int r  = idx & 255;
    int pr = r >> 4;            // pair-row 0..15
    int o  = (r & 15) * 2;      // output col 0..30 step 2
    int k  = ((pr >> 2) << 3) | (pr & 3);
    const float* kb = kern + (size_t)n * 1024;
    float4 v;
    v.x = __uint_as_float(tf32b(kb[k * 32 + o]));
    v.y = __uint_as_float(tf32b(kb[(k + 4) * 32 + o]));
    v.z = __uint_as_float(tf32b(kb[k * 32 + o + 1]));
    v.w = __uint_as_float(tf32b(kb[(k + 4) * 32 + o + 1]));
    g_bp[idx] = v;
}

// x -> tf32-rounded copy (same layout). One float4 per thread.
__global__ void convert_x_kernel(const float* __restrict__ x) {
    int idx = blockIdx.x * 256 + threadIdx.x;   // 0 .. BATCH*N_DIM/4-1
    float4 v = ((const float4*)x)[idx];
    v.x = __uint_as_float(tf32b(v.x));
    v.y = __uint_as_float(tf32b(v.y));
    v.z = __uint_as_float(tf32b(v.z));
    v.w = __uint_as_float(tf32b(v.w));
    g_xt[idx] = v;
}

// ---------------- work lists ----------------
// entry: n[0:12) | cib[12:19) | lco[19:20); list preserves sorted (ci,co) order.

__device__ int g_cnt[GROUPS];
__device__ int g_list[GROUPS * MAXL];

__global__ void build_lists_kernel(const int* __restrict__ ci, const int* __restrict__ co) {
    __shared__ int pref[NTHR];
    const int g = blockIdx.x;
    const int t = threadIdx.x;
    const int base = t * (NBLKS / NTHR);   // 16 entries per thread
    int cnt = 0;
#pragma unroll
    for (int j = 0; j < NBLKS / NTHR; j++)
        if ((co[base + j] >> 1) == g) cnt++;
    pref[t] = cnt;
    __syncthreads();
    for (int off = 1; off < NTHR; off <<= 1) {
        int v = (t >= off) ? pref[t - off] : 0;
        __syncthreads();
        pref[t] += v;
        __syncthreads();
    }
    int pos = pref[t] - cnt;
#pragma unroll
    for (int j = 0; j < NBLKS / NTHR; j++) {
        int n = base + j;
        int c = co[n];
        if ((c >> 1) == g) {
            g_list[g * MAXL + pos] = n | (ci[n] << 12) | ((c & 1) << 19);
            pos++;
        }
    }
    if (t == NTHR - 1) g_cnt[g] = pref[NTHR - 1];
}

// ---------------- per-block compute ----------------
// PTX m16n8k8.row.col A layout (row = lane>>2, col = lane&3):
//   a0=(row,col) a1=(row+8,col) a2=(row,col+4) a3=(row+8,col+4)
// B fragment: b0=(k=lane&3, n=lane>>2), b1=(k+4, n) -> one LDS.64 from paired buf.

template <int LCO>
__device__ __forceinline__ void compute_block(float (&acc)[8][4],
                                              const uint32_t (&afr)[4][4],
                                              uint32_t bpb, int kq, int nq) {
#pragma unroll
    for (int kt = 0; kt < 4; kt++) {
        uint32_t rowa = bpb + 8u * ((uint32_t)(kt * 4 + kq) * BP_PITCH + nq);
#pragma unroll
        for (int nt = 0; nt < 4; nt++) {
            uint32_t b0, b1;
            lds64(rowa + 8u * (uint32_t)(nt * 8), b0, b1);
            MMA_TF32(acc[4 * LCO + nt], afr[kt][0], afr[kt][1], afr[kt][2], afr[kt][3], b0, b1);
        }
    }
}

// x already tf32-rounded in global -> plain LDS, no cvt.
__device__ __forceinline__ void load_afrags(uint32_t (&afr)[4][4], uint32_t xs_warp,
                                            int kq, int nq) {
#pragma unroll
    for (int kt = 0; kt < 4; kt++) {
        uint32_t r0 = xs_warp + 4u * ((uint32_t)nq * XS_STRIDE + kt * 8 + kq);
        afr[kt][0] = lds32i(r0);                              // (row,   col)
        afr[kt][1] = lds32i(r0 + 8u * XS_STRIDE * 4u);        // (row+8, col)
        afr[kt][2] = lds32i(r0 + 16u);                        // (row,   col+4)
        afr[kt][3] = lds32i(r0 + 8u * XS_STRIDE * 4u + 16u);  // (row+8, col+4)
    }
}

// ---------------- main kernel ----------------
// One block per iteration. Per-iter: one commit group [X(run i+2) + B(i+2)];
// wait_group 1 at top -> group committed 2 iters ago complete: X(run i), B(i).
// XS ring 3: live runs {run(i), run(i+1)}, writing run(i+2) -> <=3 distinct.
// BP ring 4: read slot i&3, write (i+2)&3 -> disjoint, reuse sync-separated.

__global__ void __launch_bounds__(NTHR, 3)
bs_mma_kernel(const float* __restrict__ bias, float* __restrict__ out) {
    extern __shared__ char smem_raw[];
    const uint32_t base = smem_u32(smem_raw);
    int* list_s = (int*)(smem_raw + LIST_OFF);
    float* bias_s = (float*)(smem_raw + BIAS_OFF);

    const int g   = blockIdx.x;    // column group 0..63 (64 cols each)
    const int by  = blockIdx.y;    // batch tile 0..7 (128 rows)
    const int tid = threadIdx.x;
    const int w   = tid >> 5;
    const int lane = tid & 31;
    const int kq  = lane & 3;
    const int nq  = lane >> 2;

    const int cnt = g_cnt[g];
    for (int j = tid; j < cnt; j += NTHR) list_s[j] = g_list[g * MAXL + j];
    if (tid < GCOLS) bias_s[tid] = bias[g * GCOLS + tid];
    __syncthreads();

    float acc[8][4];
#pragma unroll
    for (int i = 0; i < 8; i++)
#pragma unroll
        for (int j = 0; j < 4; j++) acc[i][j] = 0.f;

    const float* xrow0 = (const float*)g_xt + (size_t)(by * 128) * N_DIM;

    auto stage_x = [&](int cib, int slot) {
        const float* src = xrow0 + cib * 32;
        uint32_t dst = base + XS_OFF + (uint32_t)slot * XS_SLOT;
#pragma unroll
        for (int j = 0; j < 4; j++) {
            int id = tid + j * NTHR;        // 0..1023 float4 slots
            int row = id >> 3, c4 = id & 7;
            cpa16(dst + (uint32_t)row * (XS_STRIDE * 4) + c4 * 16u,
                  src + (size_t)row * N_DIM + c4 * 4);
        }
    };
    // paired-B staging: thread stages float4 chunk (pr = tid>>4, c = tid&15)
    auto stage_bp = [&](int n, int slot) {
        int pr = tid >> 4, c = tid & 15;
        cpa16(base + BP_OFF + (uint32_t)slot * BP_SLOT +
                  (uint32_t)pr * (BP_PITCH * 8) + (uint32_t)c * 16u,
              g_bp + (size_t)n * 256 + tid);
    };

    if (cnt > 0) {
        int staged_cib = -1, staged_slot = XS_RING - 1;
        auto px = [&](int j) -> int {     // stage x run for entry j if new
            int e = list_s[j];
            int cib = (e >> 12) & 127;
            if (cib != staged_cib) {
                staged_slot++; if (staged_slot == XS_RING) staged_slot = 0;
                stage_x(cib, staged_slot);
                staged_cib = cib;
            }
            return staged_slot;
        };

        // Prologue: G0=[Xr(0), B0], G1=[Xr(1), B1]
        int q0 = px(0);
        stage_bp(list_s[0] & 0xFFF, 0);
        CP_COMMIT();
        int q1 = q0;
        if (cnt > 1) { q1 = px(1); stage_bp(list_s[1] & 0xFFF, 1); }
        CP_COMMIT();

        uint32_t afr[4][4];
        int frag_cib = -1;

        for (int i = 0; i < cnt; i++) {
            CP_WAIT1();            // groups committed >=2 iters ago done: X(i), B(i)
            __syncthreads();       // visible to all warps

            int qn = q1;
            if (i + 2 < cnt) { qn = px(i + 2); stage_bp(list_s[i + 2] & 0xFFF, (i + 2) & 3); }
            CP_COMMIT();

            int vi  = list_s[i];
            int cib = (vi >> 12) & 127;
            if (cib != frag_cib) {
                load_afrags(afr, base + XS_OFF + (uint32_t)q0 * XS_SLOT +
                                 (uint32_t)(16 * w) * (XS_STRIDE * 4), kq, nq);
                frag_cib = cib;
            }

            uint32_t bpb = base + BP_OFF + (uint32_t)(i & 3) * BP_SLOT;
            if ((vi >> 19) & 1) compute_block<1>(acc, afr, bpb, kq, nq);
            else                compute_block<0>(acc, afr, bpb, kq, nq);

            q0 = q1; q1 = qn;
        }
    }

    // ---- epilogue: bias + relu ----
    {
        int r = 16 * w + nq;
        size_t rb0 = (size_t)(by * 128 + r) * N_DIM + g * GCOLS;
        size_t rb1 = rb0 + 8 * (size_t)N_DIM;
#pragma unroll
        for (int nt = 0; nt < 8; nt++) {
            int c = nt * 8 + 2 * kq;
            float b0 = bias_s[c], b1 = bias_s[c + 1];
            float2 v0, v1;
            v0.x = fmaxf(acc[nt][0] + b0, 0.f);
            v0.y = fmaxf(acc[nt][1] + b1, 0.f);
            v1.x = fmaxf(acc[nt][2] + b0, 0.f);
            v1.y = fmaxf(acc[nt][3] + b1, 0.f);
            *(float2*)(out + rb0 + c) = v0;
            *(float2*)(out + rb1 + c) = v1;
        }
    }
}

extern "C" void kernel_launch(void* const* d_in, const int* in_sizes, int n_in,
                              void* d_out, int out_size) {
    const float* x    = (const float*)d_in[0];
    const float* kern = (const float*)d_in[1];
    const float* bias = (const float*)d_in[2];
    const int*   ci   = (const int*)d_in[3];
    const int*   co   = (const int*)d_in[4];
    float* out = (float*)d_out;

    cudaFuncSetAttribute(bs_mma_kernel, cudaFuncAttributeMaxDynamicSharedMemorySize, SMEM_DYN);

    convert_b_kernel<<<NBLKS, 256>>>(kern);
    convert_x_kernel<<<BATCH * N_DIM / 4 / 256, 256>>>(x);
    build_lists_kernel<<<GROUPS, NTHR>>>(ci, co);
    dim3 grid(GROUPS, BATCH / 128);
    bs_mma_kernel<<<grid, NTHR, SMEM_DYN>>>(bias, out);
}

// round 15
// speedup vs baseline: 1.2986x; 1.2986x over previous
#include <cuda_runtime.h>
#include <cstdint>

#define NB      128
#define CG      2              // block-columns per CTA
#define GROUPS  (NB / CG)      // 64
#define GCOLS   (CG * 32)      // 64
#define NTHR    128            // 4 warps, each owns 32 rows (2 m16 tiles)
#define MAXL    160
#define N_DIM   4096
#define BATCH   1024
#define NBLKS   4096

// SMEM layout (bytes, from dynamic base)
#define XS_STRIDE  36          // 36 mod 32 = 4 -> conflict-free frag loads
#define XS_SLOT    (128 * XS_STRIDE * 4)   // 18432
#define XS_RING    4
#define BP_PITCH   36          // >=32 capacity, mod 16 == 4 -> conflict-free LDS.64
#define BP_SLOT    (16 * BP_PITCH * 8)     // 4608
#define BP_RING    4
#define XS_OFF     0u
#define BP_OFF     (XS_RING * XS_SLOT)               // 73728
#define LIST_OFF   (BP_OFF + BP_RING * BP_SLOT)      // 92160
#define BIAS_OFF   (LIST_OFF + 4u * MAXL)            // 92800
#define SMEM_DYN   (BIAS_OFF + 4u * GCOLS)           // 93056 -> 2 CTAs/SM

// Pre-converted paired-tf32 kernel blocks: [block][pr (16)][float4 chunk (16)]
__device__ float4 g_bp[NBLKS * 256];            // 16 MB
// Pre-converted tf32 x, same layout as x: [BATCH][N_DIM]
__device__ float4 g_xt[BATCH * N_DIM / 4];      // 16 MB

// ---------------- helpers ----------------

__device__ __forceinline__ uint32_t smem_u32(const void* p) {
    uint32_t a;
    asm("{ .reg .u64 t; cvta.to.shared.u64 t, %1; cvt.u32.u64 %0, t; }" : "=r"(a) : "l"(p));
    return a;
}
__device__ __forceinline__ void cpa16(uint32_t dst, const void* src) {
    asm volatile("cp.async.ca.shared.global [%0], [%1], 16;" :: "r"(dst), "l"(src));
}
#define CP_COMMIT() asm volatile("cp.async.commit_group;" ::: "memory")
#define CP_WAIT0()  asm volatile("cp.async.wait_group 0;" ::: "memory")

__device__ __forceinline__ uint32_t lds32i(uint32_t a) {
    uint32_t v;
    asm volatile("ld.shared.b32 %0, [%1];" : "=r"(v) : "r"(a));
    return v;
}
__device__ __forceinline__ void lds64(uint32_t a, uint32_t& r0, uint32_t& r1) {
    asm volatile("ld.shared.v2.b32 {%0,%1}, [%2];" : "=r"(r0), "=r"(r1) : "r"(a));
}
// cvt.rna.tf32.f32 requires a .b32 destination register -> "=r"
__device__ __forceinline__ uint32_t tf32b(float a) {
    uint32_t r;
    asm("cvt.rna.tf32.f32 %0, %1;" : "=r"(r) : "f"(a));
    return r;
}

#define MMA_TF32(C, A0, A1, A2, A3, B0, B1)                                       \
    asm volatile("mma.sync.aligned.m16n8k8.row.col.f32.tf32.tf32.f32 "            \
                 "{%0,%1,%2,%3},{%4,%5,%6,%7},{%8,%9},{%0,%1,%2,%3};"             \
                 : "+f"((C)[0]), "+f"((C)[1]), "+f"((C)[2]), "+f"((C)[3])         \
                 : "r"(A0), "r"(A1), "r"(A2), "r"(A3), "r"(B0), "r"(B1))

// ---------------- prep kernels ----------------

// Reformat kern -> g_bp (tf32, paired fragment layout). One float4 per thread.
__global__ void convert_b_kernel(const float* __restrict__ kern) {
    int idx = blockIdx.x * 256 + threadIdx.x;     // 0 .. NBLKS*256-1
    int n  = idx >> 8;
    int r  = idx & 255;
    int pr = r >> 4;            // pair-row 0..15
    int o  = (r & 15) * 2;      // output col 0..30 step 2
    int k  = ((pr >> 2) << 3) | (pr & 3);
    const float* kb = kern + (size_t)n * 1024;
    float4 v;
    v.x = __uint_as_float(tf32b(kb[k * 32 + o]));
    v.y = __uint_as_float(tf32b(kb[(k + 4) * 32 + o]));
    v.z = __uint_as_float(tf32b(kb[k * 32 + o + 1]));
    v.w = __uint_as_float(tf32b(kb[(k + 4) * 32 + o + 1]));
    g_bp[idx] = v;
}

// x -> tf32-rounded copy (same layout). One float4 per thread.
__global__ void convert_x_kernel(const float* __restrict__ x) {
    int idx = blockIdx.x * 256 + threadIdx.x;   // 0 .. BATCH*N_DIM/4-1
    float4 v = ((const float4*)x)[idx];
    v.x = __uint_as_float(tf32b(v.x));
    v.y = __uint_as_float(tf32b(v.y));
    v.z = __uint_as_float(tf32b(v.z));
    v.w = __uint_as_float(tf32b(v.w));
    g_xt[idx] = v;
}

// ---------------- work lists ----------------
// entry: n[0:12) | cib[12:19) | lco[19:20); list preserves sorted (ci,co) order.

__device__ int g_cnt[GROUPS];
__device__ int g_list[GROUPS * MAXL];

#define LTHR 256
__global__ void build_lists_kernel(const int* __restrict__ ci, const int* __restrict__ co) {
    __shared__ int pref[LTHR];
    const int g = blockIdx.x;
    const int t = threadIdx.x;
    const int base = t * (NBLKS / LTHR);   // 16 entries per thread
    int cnt = 0;
#pragma unroll
    for (int j = 0; j < NBLKS / LTHR; j++)
        if ((co[base + j] >> 1) == g) cnt++;
    pref[t] = cnt;
    __syncthreads();
    for (int off = 1; off < LTHR; off <<= 1) {
        int v = (t >= off) ? pref[t - off] : 0;
        __syncthreads();
        pref[t] += v;
        __syncthreads();
    }
    int pos = pref[t] - cnt;
#pragma unroll
    for (int j = 0; j < NBLKS / LTHR; j++) {
        int n = base + j;
        int c = co[n];
        if ((c >> 1) == g) {
            g_list[g * MAXL + pos] = n | (ci[n] << 12) | ((c & 1) << 19);
            pos++;
        }
    }
    if (t == LTHR - 1) g_cnt[g] = pref[LTHR - 1];
}

// ---------------- per-block compute ----------------
// Warp w owns rows 32w..32w+31: m-tile m at rows 32w+16m (+nq, +nq+8).
// B fragment (b0=(kq,nq), b1=(kq+4,nq)) loaded ONCE per (kt,nt), reused by
// both m-tiles -> B smem traffic halved vs 16-row warps.

template <int LCO>
__device__ __forceinline__ void compute_block(float (&acc)[2][8][4],
                                              const uint32_t (&afr)[2][4][4],
                                              uint32_t bpb, int kq, int nq) {
#pragma unroll
    for (int kt = 0; kt < 4; kt++) {
        uint32_t rowa = bpb + 8u * ((uint32_t)(kt * 4 + kq) * BP_PITCH + nq);
        uint32_t b[4][2];
#pragma unroll
        for (int nt = 0; nt < 4; nt++)
            lds64(rowa + 8u * (uint32_t)(nt * 8), b[nt][0], b[nt][1]);
#pragma unroll
        for (int nt = 0; nt < 4; nt++) {
            MMA_TF32(acc[0][4 * LCO + nt], afr[0][kt][0], afr[0][kt][1],
                     afr[0][kt][2], afr[0][kt][3], b[nt][0], b[nt][1]);
            MMA_TF32(acc[1][4 * LCO + nt], afr[1][kt][0], afr[1][kt][1],
                     afr[1][kt][2], afr[1][kt][3], b[nt][0], b[nt][1]);
        }
    }
}

// x already tf32-rounded in global -> plain LDS, no cvt.
// afr[m][kt][0..3]: a0=(row,col) a1=(row+8,col) a2=(row,col+4) a3=(row+8,col+4),
// rows relative to warp base 32w + 16m.
__device__ __forceinline__ void load_afrags(uint32_t (&afr)[2][4][4], uint32_t xs_cta,
                                            int w, int kq, int nq) {
#pragma unroll
    for (int m = 0; m < 2; m++) {
        uint32_t xs_warp = xs_cta + (uint32_t)(32 * w + 16 * m) * (XS_STRIDE * 4);
#pragma unroll
        for (int kt = 0; kt < 4; kt++) {
            uint32_t r0 = xs_warp + 4u * ((uint32_t)nq * XS_STRIDE + kt * 8 + kq);
            afr[m][kt][0] = lds32i(r0);
            afr[m][kt][1] = lds32i(r0 + 8u * XS_STRIDE * 4u);
            afr[m][kt][2] = lds32i(r0 + 16u);
            afr[m][kt][3] = lds32i(r0 + 8u * XS_STRIDE * 4u + 16u);
        }
    }
}

// ---------------- main kernel ----------------
// R12's super-iteration: s handles blocks 2s, 2s+1:
//   wait_group 0 -> own copies from super s-1 done; __syncthreads -> visible;
//   stage blocks 2s+2, 2s+3 (one group); compute 2s, 2s+1.
// BP ring 4: writes {2s+2,2s+3}&3 vs reads {2s,2s+1}&3 disjoint.
// XS ring 4: live-run window = blocks 2s..2s+3 <= 4 runs.

__global__ void __launch_bounds__(NTHR, 2)
bs_mma_kernel(const float* __restrict__ bias, float* __restrict__ out) {
    extern __shared__ char smem_raw[];
    const uint32_t base = smem_u32(smem_raw);
    int* list_s = (int*)(smem_raw + LIST_OFF);
    float* bias_s = (float*)(smem_raw + BIAS_OFF);

    const int g   = blockIdx.x;    // column group 0..63 (64 cols)
    const int by  = blockIdx.y;    // batch tile 0..7 (128 rows)
    const int tid = threadIdx.x;
    const int w   = tid >> 5;      // 0..3
    const int lane = tid & 31;
    const int kq  = lane & 3;
    const int nq  = lane >> 2;

    const int cnt = g_cnt[g];
    for (int j = tid; j < cnt; j += NTHR) list_s[j] = g_list[g * MAXL + j];
    if (tid < GCOLS) bias_s[tid] = bias[g * GCOLS + tid];
    __syncthreads();

    float acc[2][8][4];
#pragma unroll
    for (int m = 0; m < 2; m++)
#pragma unroll
        for (int i = 0; i < 8; i++)
#pragma unroll
            for (int j = 0; j < 4; j++) acc[m][i][j] = 0.f;

    const float* xrow0 = (const float*)g_xt + (size_t)(by * 128) * N_DIM;

    auto stage_x = [&](int cib, int slot) {
        const float* src = xrow0 + cib * 32;
        uint32_t dst = base + XS_OFF + (uint32_t)slot * XS_SLOT;
#pragma unroll
        for (int j = 0; j < 8; j++) {
            int id = tid + j * NTHR;        // 0..1023 float4 slots
            int row = id >> 3, c4 = id & 7;
            cpa16(dst + (uint32_t)row * (XS_STRIDE * 4) + c4 * 16u,
                  src + (size_t)row * N_DIM + c4 * 4);
        }
    };
    auto stage_bp = [&](int n, int slot) {
#pragma unroll
        for (int j = 0; j < 2; j++) {
            int idx = tid + j * NTHR;       // 0..255
            int pr = idx >> 4, c = idx & 15;
            cpa16(base + BP_OFF + (uint32_t)slot * BP_SLOT +
                      (uint32_t)pr * (BP_PITCH * 8) + (uint32_t)c * 16u,
                  g_bp + (size_t)n * 256 + idx);
        }
    };

    if (cnt > 0) {
        int staged_cib = -1, staged_slot = XS_RING - 1;
        auto px = [&](int j) -> int {     // stage x run for entry j if new
            int e = list_s[j];
            int cib = (e >> 12) & 127;
            if (cib != staged_cib) {
                staged_slot++; if (staged_slot == XS_RING) staged_slot = 0;
                stage_x(cib, staged_slot);
                staged_cib = cib;
            }
            return staged_slot;
        };

        // prologue: stage blocks 0,1 (one group)
        int q0 = px(0);
        stage_bp(list_s[0] & 0xFFF, 0);
        int q1 = q0;
        if (cnt > 1) { q1 = px(1); stage_bp(list_s[1] & 0xFFF, 1); }
        CP_COMMIT();

        uint32_t afr[2][4][4];
        int frag_cib = -1;
        const int S = (cnt + 1) >> 1;

        for (int s = 0; s < S; s++) {
            const int i0 = 2 * s, i1 = 2 * s + 1;

            CP_WAIT0();            // own copies from previous super done
            __syncthreads();       // all staged data visible

            int q2 = q1, q3 = q1;
            if (i0 + 2 < cnt) { q2 = px(i0 + 2); stage_bp(list_s[i0 + 2] & 0xFFF, (i0 + 2) & 3); }
            if (i1 + 2 < cnt) { q3 = px(i1 + 2); stage_bp(list_s[i1 + 2] & 0xFFF, (i1 + 2) & 3); }
            CP_COMMIT();

            // ---- compute block i0 ----
            {
                int vi  = list_s[i0];
                int cib = (vi >> 12) & 127;
                if (cib != frag_cib) {
                    load_afrags(afr, base + XS_OFF + (uint32_t)q0 * XS_SLOT, w, kq, nq);
                    frag_cib = cib;
                }
                uint32_t bpb = base + BP_OFF + (uint32_t)(i0 & 3) * BP_SLOT;
                if ((vi >> 19) & 1) compute_block<1>(acc, afr, bpb, kq, nq);
                else                compute_block<0>(acc, afr, bpb, kq, nq);
            }
            // ---- compute block i1 ----
            if (i1 < cnt) {
                int vi  = list_s[i1];
                int cib = (vi >> 12) & 127;
                if (cib != frag_cib) {
                    load_afrags(afr, base + XS_OFF + (uint32_t)q1 * XS_SLOT, w, kq, nq);
                    frag_cib = cib;
                }
                uint32_t bpb = base + BP_OFF + (uint32_t)(i1 & 3) * BP_SLOT;
                if ((vi >> 19) & 1) compute_block<1>(acc, afr, bpb, kq, nq);
                else                compute_block<0>(acc, afr, bpb, kq, nq);
            }

            q0 = q2; q1 = q3;
        }
    }

    // ---- epilogue: bias + relu ----
    // C frag m16n8: c0,c1 -> (row=nq, col=2kq), c2,c3 -> (row=nq+8, col=2kq)
#pragma unroll
    for (int m = 0; m < 2; m++) {
        int r = by * 128 + 32 * w + 16 * m + nq;
        size_t rb0 = (size_t)r * N_DIM + g * GCOLS;
        size_t rb1 = rb0 + 8 * (size_t)N_DIM;
#pragma unroll
        for (int nt = 0; nt < 8; nt++) {
            int c = nt * 8 + 2 * kq;
            float b0 = bias_s[c], b1 = bias_s[c + 1];
            float2 v0, v1;
            v0.x = fmaxf(acc[m][nt][0] + b0, 0.f);
            v0.y = fmaxf(acc[m][nt][1] + b1, 0.f);
            v1.x = fmaxf(acc[m][nt][2] + b0, 0.f);
            v1.y = fmaxf(acc[m][nt][3] + b1, 0.f);
            *(float2*)(out + rb0 + c) = v0;
            *(float2*)(out + rb1 + c) = v1;
        }
    }
}

extern "C" void kernel_launch(void* const* d_in, const int* in_sizes, int n_in,
                              void* d_out, int out_size) {
    const float* x    = (const float*)d_in[0];
    const float* kern = (const float*)d_in[1];
    const float* bias = (const float*)d_in[2];
    const int*   ci   = (const int*)d_in[3];
    const int*   co   = (const int*)d_in[4];
    float* out = (float*)d_out;

    cudaFuncSetAttribute(bs_mma_kernel, cudaFuncAttributeMaxDynamicSharedMemorySize, SMEM_DYN);

    convert_b_kernel<<<NBLKS, 256>>>(kern);
    convert_x_kernel<<<BATCH * N_DIM / 4 / 256, 256>>>(x);
    build_lists_kernel<<<GROUPS, LTHR>>>(ci, co);
    dim3 grid(GROUPS, BATCH / 128);
    bs_mma_kernel<<<grid, NTHR, SMEM_DYN>>>(bias, out);
}

// round 16
// speedup vs baseline: 1.6132x; 1.2423x over previous
#include <cuda_runtime.h>
#include <cstdint>

#define NB      128
#define CG      2              // block-columns per CTA
#define GROUPS  (NB / CG)      // 64
#define GCOLS   (CG * 32)      // 64
#define NTHR    128            // 4 warps, each owns 32 rows (2 m16 tiles)
#define MAXL    160
#define N_DIM   4096
#define BATCH   1024
#define NBLKS   4096

// A fragments: g_xa[((rb*128 + cib)*4 + kt)*32 + lane] = float4 {a0,a1,a2,a3}
//   rb = row-block (16 rows) 0..63, a0=(rb*16+l>>2, cib*32+kt*8+(l&3)),
//   a1=+8 rows, a2=+4 cols, a3=+8r+4c.  16 MB, tf32-rounded.
__device__ float4 g_xa[64 * NB * 4 * 32];
// B fragments: g_bf[((n*4 + kt)*4 + nt)*32 + lane] = float2 {b0,b1}
//   b0 = B[kt*8+(l&3)][nt*8+(l>>2)], b1 = +4 k-rows.  16 MB, tf32-rounded.
__device__ float2 g_bf[NBLKS * 16 * 32];

// ---------------- helpers ----------------

// cvt.rna.tf32.f32 requires a .b32 destination register -> "=r"
__device__ __forceinline__ uint32_t tf32b(float a) {
    uint32_t r;
    asm("cvt.rna.tf32.f32 %0, %1;" : "=r"(r) : "f"(a));
    return r;
}

#define MMA_TF32(C, A0, A1, A2, A3, B0, B1)                                       \
    asm volatile("mma.sync.aligned.m16n8k8.row.col.f32.tf32.tf32.f32 "            \
                 "{%0,%1,%2,%3},{%4,%5,%6,%7},{%8,%9},{%0,%1,%2,%3};"             \
                 : "+f"((C)[0]), "+f"((C)[1]), "+f"((C)[2]), "+f"((C)[3])         \
                 : "r"(A0), "r"(A1), "r"(A2), "r"(A3), "r"(B0), "r"(B1))

// ---------------- prep kernels ----------------

// x -> A-fragment layout (tf32). One float4 (one lane's frag) per thread.
__global__ void convert_xa_kernel(const float* __restrict__ x) {
    int idx  = blockIdx.x * 256 + threadIdx.x;   // 0 .. 64*128*4*32-1 (1M)
    int lane = idx & 31;
    int kt   = (idx >> 5) & 3;
    int cib  = (idx >> 7) & 127;
    int rb   = idx >> 14;
    int row  = rb * 16 + (lane >> 2);
    int col  = cib * 32 + kt * 8 + (lane & 3);
    const float* xr = x + (size_t)row * N_DIM;
    float4 v;
    v.x = __uint_as_float(tf32b(xr[col]));
    v.y = __uint_as_float(tf32b(xr[col + 8 * N_DIM]));
    v.z = __uint_as_float(tf32b(xr[col + 4]));
    v.w = __uint_as_float(tf32b(xr[col + 4 + 8 * N_DIM]));
    g_xa[idx] = v;
}

// kern -> B-fragment layout (tf32). One float2 per thread.
__global__ void convert_bf_kernel(const float* __restrict__ kern) {
    int idx  = blockIdx.x * 256 + threadIdx.x;   // 0 .. NBLKS*16*32-1 (2M)
    int lane = idx & 31;
    int nt   = (idx >> 5) & 3;
    int kt   = (idx >> 7) & 3;
    int n    = idx >> 9;
    int k    = kt * 8 + (lane & 3);
    int col  = nt * 8 + (lane >> 2);
    const float* kb = kern + (size_t)n * 1024;
    float2 v;
    v.x = __uint_as_float(tf32b(kb[k * 32 + col]));
    v.y = __uint_as_float(tf32b(kb[(k + 4) * 32 + col]));
    g_bf[idx] = v;
}

// ---------------- work lists ----------------
// entry: n[0:12) | cib[12:19) | lco[19:20); list preserves sorted (ci,co) order.

__device__ int g_cnt[GROUPS];
__device__ int g_list[GROUPS * MAXL];

#define LTHR 256
__global__ void build_lists_kernel(const int* __restrict__ ci, const int* __restrict__ co) {
    __shared__ int pref[LTHR];
    const int g = blockIdx.x;
    const int t = threadIdx.x;
    const int base = t * (NBLKS / LTHR);   // 16 entries per thread
    int cnt = 0;
#pragma unroll
    for (int j = 0; j < NBLKS / LTHR; j++)
        if ((co[base + j] >> 1) == g) cnt++;
    pref[t] = cnt;
    __syncthreads();
    for (int off = 1; off < LTHR; off <<= 1) {
        int v = (t >= off) ? pref[t - off] : 0;
        __syncthreads();
        pref[t] += v;
        __syncthreads();
    }
    int pos = pref[t] - cnt;
#pragma unroll
    for (int j = 0; j < NBLKS / LTHR; j++) {
        int n = base + j;
        int c = co[n];
        if ((c >> 1) == g) {
            g_list[g * MAXL + pos] = n | (ci[n] << 12) | ((c & 1) << 19);
            pos++;
        }
    }
    if (t == LTHR - 1) g_cnt[g] = pref[LTHR - 1];
}

// ---------------- main kernel ----------------
// No datapath SMEM, no pipeline, no per-block barriers. Each warp streams
// fragment loads from L2/L1 (g_xa per-warp rows; g_bf shared across the
// CTA's 4 warps -> L1 hits) and issues MMAs. One initial __syncthreads for
// the list/bias staging only.

__global__ void __launch_bounds__(NTHR, 3)
bs_mma_kernel(const float* __restrict__ bias, float* __restrict__ out) {
    __shared__ int   list_s[MAXL];
    __shared__ float bias_s[GCOLS];

    const int g   = blockIdx.x;    // column group 0..63 (64 cols)
    const int by  = blockIdx.y;    // batch tile 0..7 (128 rows)
    const int tid = threadIdx.x;
    const int w   = tid >> 5;      // 0..3
    const int lane = tid & 31;
    const int kq  = lane & 3;
    const int nq  = lane >> 2;

    const int cnt = g_cnt[g];
    for (int j = tid; j < cnt; j += NTHR) list_s[j] = g_list[g * MAXL + j];
    if (tid < GCOLS) bias_s[tid] = bias[g * GCOLS + tid];
    __syncthreads();

    float acc[2][8][4];
#pragma unroll
    for (int m = 0; m < 2; m++)
#pragma unroll
        for (int i = 0; i < 8; i++)
#pragma unroll
            for (int j = 0; j < 4; j++) acc[m][i][j] = 0.f;

    // row-blocks for this warp's two m16 tiles
    const int rb0 = by * 8 + 2 * w;

    uint32_t afr[2][4][4];
    int frag_cib = -1;

    for (int i = 0; i < cnt; i++) {
        int vi  = list_s[i];
        int n   = vi & 0xFFF;
        int cib = (vi >> 12) & 127;
        int lco = (vi >> 19) & 1;

        if (cib != frag_cib) {
#pragma unroll
            for (int m = 0; m < 2; m++) {
                const float4* ap = g_xa + (size_t)((rb0 + m) * 128 + cib) * 128 + lane;
#pragma unroll
                for (int kt = 0; kt < 4; kt++) {
                    float4 v = ap[kt * 32];
                    afr[m][kt][0] = __float_as_uint(v.x);
                    afr[m][kt][1] = __float_as_uint(v.y);
                    afr[m][kt][2] = __float_as_uint(v.z);
                    afr[m][kt][3] = __float_as_uint(v.w);
                }
            }
            frag_cib = cib;
        }

        // load all 16 B fragments first (MLP), then MMAs
        const float2* bp = g_bf + (size_t)n * 512 + lane;
        uint32_t b[4][4][2];
#pragma unroll
        for (int kt = 0; kt < 4; kt++)
#pragma unroll
            for (int nt = 0; nt < 4; nt++) {
                float2 v = bp[(kt * 4 + nt) * 32];
                b[kt][nt][0] = __float_as_uint(v.x);
                b[kt][nt][1] = __float_as_uint(v.y);
            }

        if (lco) {
#pragma unroll
            for (int kt = 0; kt < 4; kt++)
#pragma unroll
                for (int nt = 0; nt < 4; nt++) {
                    MMA_TF32(acc[0][4 + nt], afr[0][kt][0], afr[0][kt][1],
                             afr[0][kt][2], afr[0][kt][3], b[kt][nt][0], b[kt][nt][1]);
                    MMA_TF32(acc[1][4 + nt], afr[1][kt][0], afr[1][kt][1],
                             afr[1][kt][2], afr[1][kt][3], b[kt][nt][0], b[kt][nt][1]);
                }
        } else {
#pragma unroll
            for (int kt = 0; kt < 4; kt++)
#pragma unroll
                for (int nt = 0; nt < 4; nt++) {
                    MMA_TF32(acc[0][nt], afr[0][kt][0], afr[0][kt][1],
                             afr[0][kt][2], afr[0][kt][3], b[kt][nt][0], b[kt][nt][1]);
                    MMA_TF32(acc[1][nt], afr[1][kt][0], afr[1][kt][1],
                             afr[1][kt][2], afr[1][kt][3], b[kt][nt][0], b[kt][nt][1]);
                }
        }
    }

    // ---- epilogue: bias + relu ----
    // C frag m16n8: c0,c1 -> (row=nq, col=2kq), c2,c3 -> (row=nq+8, col=2kq)
#pragma unroll
    for (int m = 0; m < 2; m++) {
        int r = by * 128 + 32 * w + 16 * m + nq;
        size_t rbase0 = (size_t)r * N_DIM + g * GCOLS;
        size_t rbase1 = rbase0 + 8 * (size_t)N_DIM;
#pragma unroll
        for (int nt = 0; nt < 8; nt++) {
            int c = nt * 8 + 2 * kq;
            float b0 = bias_s[c], b1 = bias_s[c + 1];
            float2 v0, v1;
            v0.x = fmaxf(acc[m][nt][0] + b0, 0.f);
            v0.y = fmaxf(acc[m][nt][1] + b1, 0.f);
            v1.x = fmaxf(acc[m][nt][2] + b0, 0.f);
            v1.y = fmaxf(acc[m][nt][3] + b1, 0.f);
            *(float2*)(out + rbase0 + c) = v0;
            *(float2*)(out + rbase1 + c) = v1;
        }
    }
}

extern "C" void kernel_launch(void* const* d_in, const int* in_sizes, int n_in,
                              void* d_out, int out_size) {
    const float* x    = (const float*)d_in[0];
    const float* kern = (const float*)d_in[1];
    const float* bias = (const float*)d_in[2];
    const int*   ci   = (const int*)d_in[3];
    const int*   co   = (const int*)d_in[4];
    float* out = (float*)d_out;

    convert_xa_kernel<<<64 * NB * 4 * 32 / 256, 256>>>(x);
    convert_bf_kernel<<<NBLKS * 16 * 32 / 256, 256>>>(kern);
    build_lists_kernel<<<GROUPS, LTHR>>>(ci, co);
    dim3 grid(GROUPS, BATCH / 128);
    bs_mma_kernel<<<grid, NTHR>>>(bias, out);
}